// round 9
// baseline (speedup 1.0000x reference)
#include <cuda_runtime.h>

// B=16, C=2048, H=2, HS=64, HOD=1, D_MODEL=2
// Collapsed: M_h = Wq_h Wk_h^T (2x2), g_h = Wv_h Wo_h (2,)
//   t(c,f) = xp_c^T M_h xp_f / 8;  o_h(c) = sum_{f<=c} e^t (g_h.xp_f) / sum e^t
// Taylor: e^{p.y} = sum_{j+i<=12} (p0^j/j!)(p1^i/i!) y0^j y1^i
// => causal sums = polynomial in prefix moments M_{j,i} = sum_f y0^j y1^i (j+i<=13).
// K1 (128 x 896): block (b,r) computes moments of its 4 chunks (chunk = 64 f).
// K2 (128 x 1024): MLP prefix load, row-factorized poly, exact tails (<=64).

#define CC    2048
#define NMOM  105           // #{(j,i): j+i<=13}
#define LOG2E 1.4426950408889634f

__device__ float g_mom[16][32][NMOM];   // per (batch, chunk) raw moments

__device__ __forceinline__ int midx(int j, int i) {
    return j * 14 - (j * (j - 1)) / 2 + i;
}

__device__ __forceinline__ float ex2f(float v) {
    float y;
    asm("ex2.approx.ftz.f32 %0, %1;" : "=f"(y) : "f"(v));
    return y;
}

// ---------------- K1: chunk moments ----------------
// grid = 128 (b = bid>>3, window r = bid&7), 896 threads = 28 warps.
// warp w: moment row j = w>>1, window half hf = w&1 (2 chunks, 2 f per lane each).
__global__ __launch_bounds__(896, 1)
void k1_moments(const float* __restrict__ x)
{
    __shared__ float2 sY[256];
    const int tid = threadIdx.x;
    const int b   = blockIdx.x >> 3;
    const int r   = blockIdx.x & 7;
    const int wid = tid >> 5, lane = tid & 31;

    if (tid < 256) {
        const int f = r * 256 + tid;
        const float2 v = reinterpret_cast<const float2*>(x)[b * CC + f];
        sY[tid] = make_float2(v.x + sinf((float)f), v.y + cosf((float)f));
    }
    __syncthreads();

    const int j  = wid >> 1;        // 0..13
    const int hf = wid & 1;
    float acc0[14], acc1[14];
    #pragma unroll
    for (int i = 0; i < 14; ++i) { acc0[i] = 0.f; acc1[i] = 0.f; }

    #pragma unroll
    for (int ff = 0; ff < 2; ++ff) {            // local chunk 2hf
        const float2 y = sY[hf * 128 + ff * 32 + lane];
        float c0 = 1.f;
        for (int t = 0; t < j; ++t) c0 *= y.x;  // y0^j
        float vv = c0;
        #pragma unroll
        for (int i = 0; i < 14; ++i) { acc0[i] += vv; vv *= y.y; }
    }
    #pragma unroll
    for (int ff = 2; ff < 4; ++ff) {            // local chunk 2hf+1
        const float2 y = sY[hf * 128 + ff * 32 + lane];
        float c0 = 1.f;
        for (int t = 0; t < j; ++t) c0 *= y.x;
        float vv = c0;
        #pragma unroll
        for (int i = 0; i < 14; ++i) { acc1[i] += vv; vv *= y.y; }
    }
    #pragma unroll
    for (int i = 0; i < 14; ++i) {
        float s0 = acc0[i], s1 = acc1[i];
        #pragma unroll
        for (int off = 16; off; off >>= 1) {
            s0 += __shfl_down_sync(0xffffffffu, s0, off);
            s1 += __shfl_down_sync(0xffffffffu, s1, off);
        }
        acc0[i] = s0; acc1[i] = s1;
    }
    if (lane == 0) {
        const int cb = 4 * r + 2 * hf;
        for (int i = 0; i + j <= 13; ++i) {
            const int m = midx(j, i);
            g_mom[b][cb + 0][m] = acc0[i];
            g_mom[b][cb + 1][m] = acc1[i];
        }
    }
}

// ---------------- K2: evaluation ----------------
// grid = 128 (b = bid>>3, window r = bid&7), 1024 threads.
// tasks: tid<512 poly (h = tid>>8, c_loc = tid&255); tid>=512 tails.
__global__ __launch_bounds__(1024, 1)
void k2_eval(const float* __restrict__ x,
             const float* __restrict__ Wq,
             const float* __restrict__ Wk,
             const float* __restrict__ Wv,
             const float* __restrict__ Wo,
             const float* __restrict__ Wb,
             float* __restrict__ out)
{
    __shared__ float2 sY[256];          // xp window
    __shared__ float  sPre[4][NMOM];    // prefix over chunks < 4r+quad
    __shared__ float  sM[2][2][2];      // M[h][i][j]
    __shared__ float  sG[2][2];         // g[h][i]
    __shared__ float4 sT[2][256];       // tail partials {den, a0, a1}
    __shared__ float2 sO[256];          // per-head outputs

    const int tid = threadIdx.x;
    const int b   = blockIdx.x >> 3;
    const int r   = blockIdx.x & 7;

    // ---- concurrent setup: [0,256) sY | [256,448) dots | [448,553) prefixes ----
    if (tid < 256) {
        const int f = r * 256 + tid;
        const float2 v = reinterpret_cast<const float2*>(x)[b * CC + f];
        sY[tid] = make_float2(v.x + sinf((float)f), v.y + cosf((float)f));
    } else if (tid < 448) {
        const int grp = (tid - 256) >> 4, l16 = tid & 15;
        const float *pa, *pb;
        if (grp < 8) {
            const int h = grp >> 2, i = (grp >> 1) & 1, jj = grp & 1;
            pa = Wq + h * 128 + i * 64;
            pb = Wk + h * 128 + jj * 64;
        } else {
            const int g2 = grp - 8, h = g2 >> 1, i = g2 & 1;
            pa = Wv + h * 128 + i * 64;
            pb = Wo + h * 64;
        }
        float s = 0.f;
        #pragma unroll
        for (int e = 0; e < 4; ++e) s = fmaf(pa[l16 * 4 + e], pb[l16 * 4 + e], s);
        #pragma unroll
        for (int off = 8; off; off >>= 1) s += __shfl_down_sync(0xffffffffu, s, off, 16);
        if (l16 == 0) {
            if (grp < 8) sM[grp >> 2][(grp >> 1) & 1][grp & 1] = s;
            else         sG[(grp - 8) >> 1][(grp - 8) & 1]     = s;
        }
    } else if (tid < 448 + NMOM) {
        // MLP prefix: independent loads of all needed chunk moments, then scan
        const int m    = tid - 448;
        const int base = 4 * r;
        float s = 0.f;
        #pragma unroll
        for (int k = 0; k < 32; ++k) {
            if (k >= base && k < base + 4) sPre[k - base][m] = s;
            if (k < base + 3) s += g_mom[b][k][m];
        }
    }
    __syncthreads();

    if (tid < 512) {
        // ================= poly (row-factorized) =================
        const int h = tid >> 8, c_loc = tid & 255;
        const int quad = c_loc >> 6;           // warp-uniform
        const float2 yc = sY[c_loc];
        const float p0 = (sM[h][0][0] * yc.x + sM[h][1][0] * yc.y) * 0.125f;
        const float p1 = (sM[h][0][1] * yc.x + sM[h][1][1] * yc.y) * 0.125f;

        const float INV[14] = {0.f, 1.f, 0.5f, 1.f/3.f, 0.25f, 0.2f, 1.f/6.f,
                               1.f/7.f, 0.125f, 1.f/9.f, 0.1f, 1.f/11.f,
                               1.f/12.f, 1.f/13.f};
        float aq[14], bq[14];
        aq[0] = 1.f; bq[0] = 1.f;
        #pragma unroll
        for (int t = 1; t < 14; ++t) {
            aq[t] = aq[t - 1] * p0 * INV[t];
            bq[t] = bq[t - 1] * p1 * INV[t];
        }
        const float* PRE = sPre[quad];
        float sd = 0.f, s0 = 0.f, s1 = 0.f;
        #pragma unroll
        for (int J = 0; J <= 13; ++J) {
            const int ro = J * 14 - (J * (J - 1)) / 2;
            float rt = 0.f, rs = 0.f, Plast = 0.f;
            #pragma unroll
            for (int I = 0; I + J <= 13; ++I) {
                const float P = PRE[ro + I];
                if (I + J <= 12) rt = fmaf(bq[I], P, rt);       // r_trunc
                if (I >= 1)      rs = fmaf(bq[I - 1], P, rs);   // r_shift
                if (I + J == 13) Plast = P;
            }
            const float rf = fmaf(bq[13 - J], Plast, rt);       // r_full
            if (J <= 12) sd = fmaf(aq[J], rt, sd);
            if (J >= 1)  s0 = fmaf(aq[J - 1], rf, s0);
            s1 = fmaf(aq[J], rs, s1);
        }
        __syncthreads();   // tails done

        const float4 tt = sT[h][c_loc];
        const float den = sd + tt.x;
        const float A0  = s0 + tt.y;
        const float A1  = s1 + tt.z;
        const float o   = (sG[h][0] * A0 + sG[h][1] * A1) / den;
        if (h == 0) sO[c_loc].x = o; else sO[c_loc].y = o;
    } else {
        // ================= exact tails (<=64 f) =================
        const int t = tid - 512;
        const int h = t >> 8, c_loc = t & 255;
        const float2 yc = sY[c_loc];
        const float p0 = (sM[h][0][0] * yc.x + sM[h][1][0] * yc.y) * (0.125f * LOG2E);
        const float p1 = (sM[h][0][1] * yc.x + sM[h][1][1] * yc.y) * (0.125f * LOG2E);
        float den = 0.f, a0 = 0.f, a1 = 0.f;
        for (int fl = c_loc & ~63; fl <= c_loc; ++fl) {
            const float2 yf = sY[fl];
            const float e = ex2f(fmaf(yf.x, p0, yf.y * p1));
            den += e; a0 = fmaf(e, yf.x, a0); a1 = fmaf(e, yf.y, a1);
        }
        sT[h][c_loc] = make_float4(den, a0, a1, 0.f);
        __syncthreads();   // matches poly-side barrier
    }
    __syncthreads();

    if (tid < 256) {
        const float2 o = sO[tid];
        const float b00 = __ldg(Wb + 0), b01 = __ldg(Wb + 1);
        const float b10 = __ldg(Wb + 2), b11 = __ldg(Wb + 3);
        float2 res;
        res.x = fmaf(o.x, b00, o.y * b10);
        res.y = fmaf(o.x, b01, o.y * b11);
        reinterpret_cast<float2*>(out)[b * CC + r * 256 + tid] = res;
    }
}

extern "C" void kernel_launch(void* const* d_in, const int* in_sizes, int n_in,
                              void* d_out, int out_size)
{
    const float* x  = (const float*)d_in[0];
    const float* Wq = (const float*)d_in[1];
    const float* Wk = (const float*)d_in[2];
    const float* Wv = (const float*)d_in[3];
    const float* Wo = (const float*)d_in[4];
    const float* Wb = (const float*)d_in[5];
    float* out = (float*)d_out;

    k1_moments<<<128, 896>>>(x);
    k2_eval<<<128, 1024>>>(x, Wq, Wk, Wv, Wo, Wb, out);
}

// round 11
// speedup vs baseline: 2.0519x; 2.0519x over previous
#include <cuda_runtime.h>

// B=16, C=2048, H=2, HS=64, HOD=1, D_MODEL=2
// Collapsed: M_h = Wq_h Wk_h^T (2x2), g_h = Wv_h Wo_h (2,)
//   t(c,f) = xp_c^T M_h xp_f / 8;  o_h(c) = sum_{f<=c} e^t (g_h.xp_f) / sum e^t
// Taylor: e^{p.y} = sum_{j+i<=12} (p0^j/j!)(p1^i/i!) y0^j y1^i
// => causal sums = polynomial in prefix moments M_{j,i} = sum_f y0^j y1^i (j+i<=13).
// K1 (128 x 512): power tables in smem -> each thread one (chunk, moment) dot.
// K2 (128 x 1024): R6 skeleton (uniform barriers, MLP prefix) + row-factored poly.

#define CC    2048
#define NMOM  105           // #{(j,i): j+i<=13}
#define LOG2E 1.4426950408889634f

__device__ float g_mom[16][32][NMOM];   // per (batch, chunk64) raw moments

__device__ __forceinline__ float ex2f(float v) {
    float y;
    asm("ex2.approx.ftz.f32 %0, %1;" : "=f"(y) : "f"(v));
    return y;
}

// ---------------- K1: chunk moments via smem power tables ----------------
// grid = 128 (b = bid>>3, window r = bid&7), 512 threads.
__global__ __launch_bounds__(512, 1)
void k1_moments(const float* __restrict__ x)
{
    __shared__ float sP0[4][14][67];   // y0^j, pad 67 (bank-conflict free)
    __shared__ float sP1[4][14][67];   // y1^i

    const int tid = threadIdx.x;
    const int b   = blockIdx.x >> 3;
    const int r   = blockIdx.x & 7;

    if (tid < 256) {
        const int ch = tid >> 6, fl = tid & 63;
        const int f  = r * 256 + tid;
        const float2 v = reinterpret_cast<const float2*>(x)[b * CC + f];
        const float y0 = v.x + sinf((float)f);
        const float y1 = v.y + cosf((float)f);
        float p = 1.f, q = 1.f;
        #pragma unroll
        for (int j = 0; j < 14; ++j) {
            sP0[ch][j][fl] = p;  p *= y0;
            sP1[ch][j][fl] = q;  q *= y1;
        }
    }
    __syncthreads();

    if (tid < 420) {
        const int ch = tid / 105;
        const int m  = tid % 105;
        int j = 0, mm = m;
        while (mm >= 14 - j) { mm -= 14 - j; ++j; }   // decode (j, i)
        const int i = mm;
        const float* __restrict__ P0 = sP0[ch][j];
        const float* __restrict__ P1 = sP1[ch][i];
        float a0 = 0.f, a1 = 0.f, a2 = 0.f, a3 = 0.f;
        #pragma unroll
        for (int f = 0; f < 64; f += 4) {
            a0 = fmaf(P0[f + 0], P1[f + 0], a0);
            a1 = fmaf(P0[f + 1], P1[f + 1], a1);
            a2 = fmaf(P0[f + 2], P1[f + 2], a2);
            a3 = fmaf(P0[f + 3], P1[f + 3], a3);
        }
        g_mom[b][4 * r + ch][m] = (a0 + a1) + (a2 + a3);
    }
}

// ---------------- K2: evaluation ----------------
// grid = 128 (b = bid>>3, window r = bid&7), 1024 threads.
// sub = tid>>8: {0: h0-poly, 1: h1-poly, 2: h0-tail, 3: h1-tail}; uniform barriers.
__global__ __launch_bounds__(1024, 1)
void k2_eval(const float* __restrict__ x,
             const float* __restrict__ Wq,
             const float* __restrict__ Wk,
             const float* __restrict__ Wv,
             const float* __restrict__ Wo,
             const float* __restrict__ Wb,
             float* __restrict__ out)
{
    __shared__ float2 sY[256];          // xp window
    __shared__ float  sPre[4][NMOM];    // prefix over chunks < 4r+quad
    __shared__ float  sM[2][2][2];      // M[h][i][j]
    __shared__ float  sG[2][2];         // g[h][i]
    __shared__ float4 sPart[256][4];    // per-(c,sub) partials {den/sd, a0/s0, a1/s1}
    __shared__ float2 sO[256];          // per-head outputs

    const int tid = threadIdx.x;
    const int b   = blockIdx.x >> 3;
    const int r   = blockIdx.x & 7;

    // ---- concurrent setup: [0,256) sY | [256,448) dots | [448,553) prefixes ----
    if (tid < 256) {
        const int f = r * 256 + tid;
        const float2 v = reinterpret_cast<const float2*>(x)[b * CC + f];
        sY[tid] = make_float2(v.x + sinf((float)f), v.y + cosf((float)f));
    } else if (tid < 448) {
        const int grp = (tid - 256) >> 4, l16 = tid & 15;
        const float *pa, *pb;
        if (grp < 8) {
            const int h = grp >> 2, i = (grp >> 1) & 1, jj = grp & 1;
            pa = Wq + h * 128 + i * 64;
            pb = Wk + h * 128 + jj * 64;
        } else {
            const int g2 = grp - 8, h = g2 >> 1, i = g2 & 1;
            pa = Wv + h * 128 + i * 64;
            pb = Wo + h * 64;
        }
        float s = 0.f;
        #pragma unroll
        for (int e = 0; e < 4; ++e) s = fmaf(pa[l16 * 4 + e], pb[l16 * 4 + e], s);
        #pragma unroll
        for (int off = 8; off; off >>= 1) s += __shfl_down_sync(0xffffffffu, s, off, 16);
        if (l16 == 0) {
            if (grp < 8) sM[grp >> 2][(grp >> 1) & 1][grp & 1] = s;
            else         sG[(grp - 8) >> 1][(grp - 8) & 1]     = s;
        }
    } else if (tid < 448 + NMOM) {
        // MLP prefix: unconditional preload of all 32 chunk values, then scan
        const int m = tid - 448;
        float v[32];
        #pragma unroll
        for (int k = 0; k < 32; ++k) v[k] = g_mom[b][k][m];
        float s = 0.f;
        const int base = 4 * r;
        #pragma unroll
        for (int k = 0; k < 32; ++k) {
            if (k >= base && k < base + 4) sPre[k - base][m] = s;
            if (k < base + 3) s += v[k];
        }
    }
    __syncthreads();

    const int c_loc = tid & 255;
    const int sub   = tid >> 8;
    const int h     = sub & 1;
    const int type  = sub >> 1;         // 0 = poly, 1 = tail
    const int quad  = c_loc >> 6;       // warp-uniform

    const float2 yc = sY[c_loc];
    const float p0 = (sM[h][0][0] * yc.x + sM[h][1][0] * yc.y) * 0.125f;
    const float p1 = (sM[h][0][1] * yc.x + sM[h][1][1] * yc.y) * 0.125f;

    if (type == 0) {
        // ---- polynomial part (row-factorized): sums over f < 64*(4r+quad) ----
        const float INV[14] = {0.f, 1.f, 0.5f, 1.f/3.f, 0.25f, 0.2f, 1.f/6.f,
                               1.f/7.f, 0.125f, 1.f/9.f, 0.1f, 1.f/11.f,
                               1.f/12.f, 1.f/13.f};
        float aq[14], bq[14];
        aq[0] = 1.f; bq[0] = 1.f;
        #pragma unroll
        for (int t = 1; t < 14; ++t) {
            aq[t] = aq[t - 1] * p0 * INV[t];
            bq[t] = bq[t - 1] * p1 * INV[t];
        }
        const float* PRE = sPre[quad];
        float sd = 0.f, s0 = 0.f, s1 = 0.f;
        #pragma unroll
        for (int J = 0; J <= 13; ++J) {
            const int ro = J * 14 - (J * (J - 1)) / 2;
            float rt = 0.f, rs = 0.f, Plast = 0.f;
            #pragma unroll
            for (int I = 0; I + J <= 13; ++I) {
                const float P = PRE[ro + I];
                if (I + J <= 12) rt = fmaf(bq[I], P, rt);       // r_trunc
                if (I >= 1)      rs = fmaf(bq[I - 1], P, rs);   // r_shift
                if (I + J == 13) Plast = P;
            }
            const float rf = fmaf(bq[13 - J], Plast, rt);       // r_full
            if (J <= 12) sd = fmaf(aq[J], rt, sd);
            if (J >= 1)  s0 = fmaf(aq[J - 1], rf, s0);
            s1 = fmaf(aq[J], rs, s1);
        }
        sPart[c_loc][sub] = make_float4(sd, s0, s1, 0.f);
    } else {
        // ---- exact tail over f in [64*chunk(c), c]  (<= 64 iterations) ----
        const float pd0 = p0 * LOG2E, pd1 = p1 * LOG2E;
        float den = 0.f, a0 = 0.f, a1 = 0.f;
        for (int fl = c_loc & ~63; fl <= c_loc; ++fl) {
            const float2 yf = sY[fl];
            const float e = ex2f(fmaf(yf.x, pd0, yf.y * pd1));
            den += e; a0 = fmaf(e, yf.x, a0); a1 = fmaf(e, yf.y, a1);
        }
        sPart[c_loc][sub] = make_float4(den, a0, a1, 0.f);
    }
    __syncthreads();

    if (type == 0) {
        const float4 mine = sPart[c_loc][sub];
        const float4 tt   = sPart[c_loc][2 + h];
        const float den = mine.x + tt.x;
        const float A0  = mine.y + tt.y;
        const float A1  = mine.z + tt.z;
        const float o   = (sG[h][0] * A0 + sG[h][1] * A1) / den;
        if (h == 0) sO[c_loc].x = o; else sO[c_loc].y = o;
    }
    __syncthreads();

    if (tid < 256) {
        const float2 o = sO[tid];
        const float b00 = __ldg(Wb + 0), b01 = __ldg(Wb + 1);
        const float b10 = __ldg(Wb + 2), b11 = __ldg(Wb + 3);
        float2 res;
        res.x = fmaf(o.x, b00, o.y * b10);
        res.y = fmaf(o.x, b01, o.y * b11);
        reinterpret_cast<float2*>(out)[b * CC + r * 256 + tid] = res;
    }
}

extern "C" void kernel_launch(void* const* d_in, const int* in_sizes, int n_in,
                              void* d_out, int out_size)
{
    const float* x  = (const float*)d_in[0];
    const float* Wq = (const float*)d_in[1];
    const float* Wk = (const float*)d_in[2];
    const float* Wv = (const float*)d_in[3];
    const float* Wo = (const float*)d_in[4];
    const float* Wb = (const float*)d_in[5];
    float* out = (float*)d_out;

    k1_moments<<<128, 512>>>(x);
    k2_eval<<<128, 1024>>>(x, Wq, Wk, Wv, Wo, Wb, out);
}